// round 11
// baseline (speedup 1.0000x reference)
#include <cuda_runtime.h>
#include <cstdint>

#define HH     480
#define WW     640
#define DIMC   32
#define NB     8
#define HWSZ   (HH * WW)          // 307,200
#define NPIX   (NB * HWSZ)        // 2,457,600
#define BSHIFT 8
#define BSITES 256                // sites per bucket (contiguous in plane)
#define NBUCK  (NPIX / BSITES)    // 9600
#define NSUB   8                  // sub-cursors per bucket (contention / 8)
#define CAP    96                 // slots per sub-cursor (lambda=26, ~14 sigma)

__device__ int g_off[NB];                      // canonical int32 batch offsets
__device__ int g_cur[NBUCK * NSUB];            // cursors (memset per call, 300KB)
__device__ int g_rec[NBUCK * NSUB * CAP];      // packed records (e<<8)|site, 29.5MB

// Normalize offsets to int32 whether harness stored int64 or int32.
// int64 LE: words = [v0, 0, v1, 0, ...]; int32: [v0, v1, ...] with v1 != 0.
__global__ void prep_offsets_kernel(const int* __restrict__ o32)
{
    bool is64 = (o32[1] == 0);
#pragma unroll
    for (int i = 0; i < NB; i++)
        g_off[i] = is64 ? o32[2 * i] : o32[i];
}

__device__ __forceinline__ void bucket_one(int e, float ex, float ey)
{
    // jnp.round == round-half-even == __float2int_rn; then clip
    int x = __float2int_rn(ex * (float)WW);
    int y = __float2int_rn(ey * (float)HH);
    x = min(max(x, 0), WW - 1);
    y = min(max(y, 0), HH - 1);

    // searchsorted(offsets, e, side='right')
    int b = 0;
#pragma unroll
    for (int i = 0; i < NB; i++)
        b += (e >= g_off[i]) ? 1 : 0;

    int pix    = (b * HH + y) * WW + x;
    int site   = pix & (BSITES - 1);
    int bucket = pix >> BSHIFT;
    int cur    = bucket * NSUB + (e & (NSUB - 1));

    int slot = atomicAdd(&g_cur[cur], 1);
    g_rec[cur * CAP + slot] = (e << 8) | site;
}

// Single pass: 2 events per thread (one float4 = events 2t, 2t+1),
// two independent atomic chains in flight.
__global__ void bucket_kernel(const float* __restrict__ events, int n)
{
    int t  = blockIdx.x * blockDim.x + threadIdx.x;
    int e0 = 2 * t;
    if (e0 >= n) return;

    float4 v = __ldg((const float4*)events + t);
    bucket_one(e0, v.x, v.y);
    if (e0 + 1 < n) bucket_one(e0 + 1, v.z, v.w);
}

// One block per bucket: stage the 8 sub-segments into a contiguous SMEM list,
// accumulate features in SMEM ([site*33+d]; slot d=32 holds the hit count —
// bank-safe in both accumulate and transpose-read phases), then write
// normalized [B, D, H, W] output directly, coalesced.
__global__ void __launch_bounds__(256) accum_kernel(const float* __restrict__ feat,
                                                    float* __restrict__ out)
{
    __shared__ float s[BSITES * 33];       // 33.8 KB (col 32 = count)
    __shared__ float sinv[BSITES];
    __shared__ int   recs[NSUB * CAP];     // 3 KB
    __shared__ int   cbase[NSUB + 1];

    int tid = threadIdx.x;
    int b   = blockIdx.x;

    for (int i = tid; i < BSITES * 33; i += 256) s[i] = 0.0f;
    if (tid == 0) {
        int run = 0;
#pragma unroll
        for (int ss = 0; ss < NSUB; ss++) {
            cbase[ss] = run;
            run += g_cur[b * NSUB + ss];
        }
        cbase[NSUB] = run;
    }
    __syncthreads();

#pragma unroll
    for (int ss = 0; ss < NSUB; ss++) {
        int c = cbase[ss + 1] - cbase[ss];
        for (int i = tid; i < c; i += 256)
            recs[cbase[ss] + i] = g_rec[(b * NSUB + ss) * CAP + i];
    }
    __syncthreads();

    int total = cbase[NSUB] * 8;
    // 8 threads per event: group gathers one full 128B feature line.
    // Process two records per iteration with both loads issued up front (MLP=2).
    for (int i = tid; i < total; i += 512) {
        int  r0    = recs[i >> 3];
        int  part0 = i & 7;
        float4 f0  = __ldg((const float4*)feat + (size_t)(r0 >> 8) * 8 + part0);

        int  j   = i + 256;
        bool has = (j < total);
        int  r1 = 0, part1 = 0;
        float4 f1;
        if (has) {
            r1    = recs[j >> 3];
            part1 = j & 7;
            f1    = __ldg((const float4*)feat + (size_t)(r1 >> 8) * 8 + part1);
        }

        {
            float* p = &s[(r0 & (BSITES - 1)) * 33 + part0 * 4];
            atomicAdd(p + 0, f0.x);
            atomicAdd(p + 1, f0.y);
            atomicAdd(p + 2, f0.z);
            atomicAdd(p + 3, f0.w);
            if (part0 == 0) atomicAdd(&s[(r0 & (BSITES - 1)) * 33 + 32], 1.0f);
        }
        if (has) {
            float* p = &s[(r1 & (BSITES - 1)) * 33 + part1 * 4];
            atomicAdd(p + 0, f1.x);
            atomicAdd(p + 1, f1.y);
            atomicAdd(p + 2, f1.z);
            atomicAdd(p + 3, f1.w);
            if (part1 == 0) atomicAdd(&s[(r1 & (BSITES - 1)) * 33 + 32], 1.0f);
        }
    }
    __syncthreads();

    sinv[tid] = 1.0f / fmaxf(s[tid * 33 + 32], 1.0f);
    __syncthreads();

    int pix0 = b << BSHIFT;
    int bb   = pix0 / HWSZ;
    int rem  = pix0 - bb * HWSZ;                 // multiple of 256
    float* obase = out + (size_t)bb * DIMC * HWSZ + rem;

    int w = tid >> 5, lane = tid & 31;
#pragma unroll
    for (int it = 0; it < 4; it++) {
        int d = w + it * 8;
        float* od = obase + (size_t)d * HWSZ;
#pragma unroll
        for (int sb = 0; sb < BSITES; sb += 32) {
            int site = sb + lane;
            od[site] = s[site * 33 + d] * sinv[site];   // conflict-free
        }
    }
}

extern "C" void kernel_launch(void* const* d_in, const int* in_sizes, int n_in,
                              void* d_out, int out_size)
{
    const float* events   = (const float*)d_in[0];
    const float* features = (const float*)d_in[1];
    const int*   offs_raw = (const int*)d_in[2];
    int n = in_sizes[0] / 2;

    void* cur_ptr = nullptr;
    cudaGetSymbolAddress(&cur_ptr, g_cur);
    cudaMemsetAsync(cur_ptr, 0, NBUCK * NSUB * sizeof(int), 0);

    prep_offsets_kernel<<<1, 1>>>(offs_raw);

    int nt = (n + 1) / 2;                        // 2 events per thread
    bucket_kernel<<<(nt + 255) / 256, 256>>>(events, n);

    accum_kernel<<<NBUCK, 256>>>(features, (float*)d_out);
}